// round 2
// baseline (speedup 1.0000x reference)
#include <cuda_runtime.h>

#define BATCH   4
#define SEQ     2048
#define DIM     512
#define HEADS   8
#define DHEAD   64
#define INNER   512           // HEADS * DHEAD
#define QKV_W   (3 * INNER)   // 1536
#define SCALE_F 0.125f        // 64^-0.5

#define BQ  32
#define BKV 64

// Scratch (no allocations allowed): qkv projection + attention output
__device__ float g_qkv[(size_t)BATCH * SEQ * QKV_W];   // 12.58M floats
__device__ float g_attn[(size_t)BATCH * SEQ * INNER];  // 4.19M floats

// ---------------------------------------------------------------------------
// SGEMM: C[M,N] = A[M,K] @ B[K,N] (+ bias). 128x128 block, BK=8, 8x8/thread.
// mode 1: C := g_qkv   (so host never needs cudaGetSymbolAddress)
// mode 2: A := g_attn
// ---------------------------------------------------------------------------
__global__ __launch_bounds__(256) void sgemm_kernel(
    int M, int N, int K,
    const float* __restrict__ A,
    const float* __restrict__ B,
    const float* __restrict__ bias,
    float* __restrict__ C,
    int mode)
{
    if (mode == 1) C = g_qkv;
    if (mode == 2) A = g_attn;

    __shared__ float As[8][128];   // stored K-major (transposed on load)
    __shared__ float Bs[8][128];

    const int tid  = threadIdx.x;
    const int tRow = tid >> 4;     // 0..15
    const int tCol = tid & 15;     // 0..15

    const float* Ab = A + (size_t)blockIdx.y * 128 * K;
    const float* Bb = B + (size_t)blockIdx.x * 128;

    float acc[8][8];
    #pragma unroll
    for (int i = 0; i < 8; i++)
        #pragma unroll
        for (int j = 0; j < 8; j++) acc[i][j] = 0.f;

    const int aRow = tid >> 1;            // 0..127
    const int aCol = (tid & 1) << 2;      // 0 or 4
    const int bRow = tid >> 5;            // 0..7
    const int bCol = (tid & 31) << 2;     // 0..124

    for (int k0 = 0; k0 < K; k0 += 8) {
        float4 av = *(const float4*)(Ab + (size_t)aRow * K + k0 + aCol);
        As[aCol + 0][aRow] = av.x;
        As[aCol + 1][aRow] = av.y;
        As[aCol + 2][aRow] = av.z;
        As[aCol + 3][aRow] = av.w;
        *(float4*)&Bs[bRow][bCol] =
            *(const float4*)(Bb + (size_t)(k0 + bRow) * N + bCol);
        __syncthreads();

        #pragma unroll
        for (int k = 0; k < 8; k++) {
            float4 a0 = *(float4*)&As[k][tRow * 8];
            float4 a1 = *(float4*)&As[k][tRow * 8 + 4];
            float4 b0 = *(float4*)&Bs[k][tCol * 8];
            float4 b1 = *(float4*)&Bs[k][tCol * 8 + 4];
            float ra[8] = {a0.x, a0.y, a0.z, a0.w, a1.x, a1.y, a1.z, a1.w};
            float rb[8] = {b0.x, b0.y, b0.z, b0.w, b1.x, b1.y, b1.z, b1.w};
            #pragma unroll
            for (int i = 0; i < 8; i++)
                #pragma unroll
                for (int j = 0; j < 8; j++)
                    acc[i][j] += ra[i] * rb[j];
        }
        __syncthreads();
    }

    const int row0 = blockIdx.y * 128 + tRow * 8;
    const int col0 = blockIdx.x * 128 + tCol * 8;
    float bv[8] = {0, 0, 0, 0, 0, 0, 0, 0};
    if (bias) {
        #pragma unroll
        for (int j = 0; j < 8; j++) bv[j] = bias[col0 + j];
    }
    #pragma unroll
    for (int i = 0; i < 8; i++) {
        float4 c0 = {acc[i][0] + bv[0], acc[i][1] + bv[1],
                     acc[i][2] + bv[2], acc[i][3] + bv[3]};
        float4 c1 = {acc[i][4] + bv[4], acc[i][5] + bv[5],
                     acc[i][6] + bv[6], acc[i][7] + bv[7]};
        *(float4*)(C + (size_t)(row0 + i) * N + col0)     = c0;
        *(float4*)(C + (size_t)(row0 + i) * N + col0 + 4) = c1;
    }
}

// ---------------------------------------------------------------------------
// Flash attention (fp32, online softmax).
// Block: one (b,h) x 32 query rows. Loops over 32 KV tiles of 64 keys.
// 256 threads: ty=tid/16 (16), tx=tid%16 (16); thread tile = 2 q-rows x 4 cols.
// Smem: Qs 8KB + KP 16.25KB (K tile, reused as P) + Vs 16KB = 41216 B < 48KB.
// ---------------------------------------------------------------------------
__global__ __launch_bounds__(256) void attn_kernel()
{
    __shared__ float Qs[BQ][64];
    __shared__ float KP[BKV][65];   // K tile [key][d] (pad 65); reused as P[q][key]
    __shared__ float Vs[BKV][64];   // V tile [key][d]

    const int tid = threadIdx.x;
    const int tx  = tid & 15;
    const int ty  = tid >> 4;
    const int qt  = blockIdx.x;          // 0..63
    const int bh  = blockIdx.y;          // 0..31
    const int b   = bh >> 3;
    const int h   = bh & 7;

    const float* base = g_qkv + (size_t)b * SEQ * QKV_W + h * DHEAD;
    const int n0 = qt * BQ;

    // Load Q tile, pre-scaled by SCALE
    #pragma unroll
    for (int r = 0; r < 2; r++) {
        int idx = tid + r * 256;          // 0..511
        int row = idx >> 4;               // 0..31
        int c4  = (idx & 15) << 2;        // 0..60
        float4 q = *(const float4*)(base + (size_t)(n0 + row) * QKV_W + c4);
        q.x *= SCALE_F; q.y *= SCALE_F; q.z *= SCALE_F; q.w *= SCALE_F;
        *(float4*)&Qs[row][c4] = q;
    }

    float m[2] = {-1e30f, -1e30f};
    float l[2] = {0.f, 0.f};
    float o[2][4];
    #pragma unroll
    for (int i = 0; i < 2; i++)
        #pragma unroll
        for (int j = 0; j < 4; j++) o[i][j] = 0.f;

    for (int kt = 0; kt < SEQ / BKV; kt++) {
        const int kn0 = kt * BKV;
        // Load K, V tiles (coalesced float4 reads)
        #pragma unroll
        for (int r = 0; r < 4; r++) {
            int idx = tid + r * 256;       // 0..1023
            int row = idx >> 4;            // 0..63
            int c4  = (idx & 15) << 2;     // 0..60
            float4 kv = *(const float4*)(base + INNER +
                         (size_t)(kn0 + row) * QKV_W + c4);
            KP[row][c4 + 0] = kv.x; KP[row][c4 + 1] = kv.y;
            KP[row][c4 + 2] = kv.z; KP[row][c4 + 3] = kv.w;
            *(float4*)&Vs[row][c4] = *(const float4*)(base + 2 * INNER +
                         (size_t)(kn0 + row) * QKV_W + c4);
        }
        __syncthreads();

        // S = Q @ K^T  (Q pre-scaled)
        float s[2][4] = {{0.f, 0.f, 0.f, 0.f}, {0.f, 0.f, 0.f, 0.f}};
        #pragma unroll 8
        for (int d = 0; d < 64; d++) {
            float q0 = Qs[ty * 2][d];
            float q1 = Qs[ty * 2 + 1][d];
            #pragma unroll
            for (int j = 0; j < 4; j++) {
                float kv = KP[tx * 4 + j][d];
                s[0][j] += q0 * kv;
                s[1][j] += q1 * kv;
            }
        }

        // Online softmax (row stats reduced over the 16 tx lanes)
        #pragma unroll
        for (int i = 0; i < 2; i++) {
            float rmax = fmaxf(fmaxf(s[i][0], s[i][1]), fmaxf(s[i][2], s[i][3]));
            #pragma unroll
            for (int off = 1; off < 16; off <<= 1)
                rmax = fmaxf(rmax, __shfl_xor_sync(0xffffffffu, rmax, off));
            float newm  = fmaxf(m[i], rmax);
            float alpha = __expf(m[i] - newm);
            float rsum  = 0.f;
            #pragma unroll
            for (int j = 0; j < 4; j++) {
                s[i][j] = __expf(s[i][j] - newm);
                rsum   += s[i][j];
            }
            #pragma unroll
            for (int off = 1; off < 16; off <<= 1)
                rsum += __shfl_xor_sync(0xffffffffu, rsum, off);
            l[i] = l[i] * alpha + rsum;
            m[i] = newm;
            #pragma unroll
            for (int j = 0; j < 4; j++) o[i][j] *= alpha;
        }

        __syncthreads();                 // all threads done reading K
        // Write P into KP (rows 0..31)
        #pragma unroll
        for (int i = 0; i < 2; i++)
            #pragma unroll
            for (int j = 0; j < 4; j++)
                KP[ty * 2 + i][tx * 4 + j] = s[i][j];
        __syncthreads();

        // O += P @ V
        #pragma unroll 4
        for (int jj = 0; jj < BKV; jj++) {
            float p0 = KP[ty * 2][jj];
            float p1 = KP[ty * 2 + 1][jj];
            float4 v = *(float4*)&Vs[jj][tx * 4];
            o[0][0] += p0 * v.x; o[0][1] += p0 * v.y;
            o[0][2] += p0 * v.z; o[0][3] += p0 * v.w;
            o[1][0] += p1 * v.x; o[1][1] += p1 * v.y;
            o[1][2] += p1 * v.z; o[1][3] += p1 * v.w;
        }
        __syncthreads();
    }

    // Normalize and write to g_attn in [b, n, h*64+d] layout
    #pragma unroll
    for (int i = 0; i < 2; i++) {
        float inv = 1.f / l[i];
        float4 ov = {o[i][0] * inv, o[i][1] * inv, o[i][2] * inv, o[i][3] * inv};
        *(float4*)(g_attn + (size_t)(b * SEQ + n0 + ty * 2 + i) * INNER +
                   h * DHEAD + tx * 4) = ov;
    }
}

// ---------------------------------------------------------------------------
extern "C" void kernel_launch(void* const* d_in, const int* in_sizes, int n_in,
                              void* d_out, int out_size)
{
    const float* x     = (const float*)d_in[0];   // [4,2048,512]
    const float* w_qkv = (const float*)d_in[1];   // [512,1536]
    const float* w_out = (const float*)d_in[2];   // [512,512]
    const float* b_out = (const float*)d_in[3];   // [512]
    float* out = (float*)d_out;                   // [4,2048,512]

    const int M = BATCH * SEQ;                    // 8192

    // 1) qkv = x @ w_qkv  -> g_qkv (mode 1)
    dim3 g1(QKV_W / 128, M / 128);                // (12, 64)
    sgemm_kernel<<<g1, 256>>>(M, QKV_W, DIM, x, w_qkv, nullptr, nullptr, 1);

    // 2) attention -> g_attn
    dim3 g2(SEQ / BQ, BATCH * HEADS);             // (64, 32)
    attn_kernel<<<g2, 256>>>();

    // 3) out = g_attn @ w_out + b_out (mode 2)
    dim3 g3(DIM / 128, M / 128);                  // (4, 64)
    sgemm_kernel<<<g3, 256>>>(M, DIM, INNER, nullptr, w_out, b_out, out, 2);
}

// round 5
// speedup vs baseline: 3.1007x; 3.1007x over previous
#include <cuda_runtime.h>

#define BATCH   4
#define SEQ     2048
#define DIM     512
#define HEADS   8
#define DHEAD   64
#define INNER   512           // HEADS * DHEAD
#define QKV_W   (3 * INNER)   // 1536
#define SCALE_F 0.125f        // 64^-0.5

// Scratch (no allocations allowed): qkv projection + attention output
__device__ float g_qkv[(size_t)BATCH * SEQ * QKV_W];   // 12.58M floats
__device__ float g_attn[(size_t)BATCH * SEQ * INNER];  // 4.19M floats

// ---------------------------------------------------------------------------
// SGEMM: C[M,N] = A[M,K] @ B[K,N] (+ bias). 128x128 block, BK=8, 8x8/thread.
// mode 1: C := g_qkv ; mode 2: A := g_attn
// ---------------------------------------------------------------------------
__global__ __launch_bounds__(256) void sgemm_kernel(
    int M, int N, int K,
    const float* __restrict__ A,
    const float* __restrict__ B,
    const float* __restrict__ bias,
    float* __restrict__ C,
    int mode)
{
    if (mode == 1) C = g_qkv;
    if (mode == 2) A = g_attn;

    __shared__ float As[8][128];
    __shared__ float Bs[8][128];

    const int tid  = threadIdx.x;
    const int tRow = tid >> 4;
    const int tCol = tid & 15;

    const float* Ab = A + (size_t)blockIdx.y * 128 * K;
    const float* Bb = B + (size_t)blockIdx.x * 128;

    float acc[8][8];
    #pragma unroll
    for (int i = 0; i < 8; i++)
        #pragma unroll
        for (int j = 0; j < 8; j++) acc[i][j] = 0.f;

    const int aRow = tid >> 1;
    const int aCol = (tid & 1) << 2;
    const int bRow = tid >> 5;
    const int bCol = (tid & 31) << 2;

    for (int k0 = 0; k0 < K; k0 += 8) {
        float4 av = *(const float4*)(Ab + (size_t)aRow * K + k0 + aCol);
        As[aCol + 0][aRow] = av.x;
        As[aCol + 1][aRow] = av.y;
        As[aCol + 2][aRow] = av.z;
        As[aCol + 3][aRow] = av.w;
        *(float4*)&Bs[bRow][bCol] =
            *(const float4*)(Bb + (size_t)(k0 + bRow) * N + bCol);
        __syncthreads();

        #pragma unroll
        for (int k = 0; k < 8; k++) {
            float4 a0 = *(float4*)&As[k][tRow * 8];
            float4 a1 = *(float4*)&As[k][tRow * 8 + 4];
            float4 b0 = *(float4*)&Bs[k][tCol * 8];
            float4 b1 = *(float4*)&Bs[k][tCol * 8 + 4];
            float ra[8] = {a0.x, a0.y, a0.z, a0.w, a1.x, a1.y, a1.z, a1.w};
            float rb[8] = {b0.x, b0.y, b0.z, b0.w, b1.x, b1.y, b1.z, b1.w};
            #pragma unroll
            for (int i = 0; i < 8; i++)
                #pragma unroll
                for (int j = 0; j < 8; j++)
                    acc[i][j] += ra[i] * rb[j];
        }
        __syncthreads();
    }

    const int row0 = blockIdx.y * 128 + tRow * 8;
    const int col0 = blockIdx.x * 128 + tCol * 8;
    float bv[8] = {0, 0, 0, 0, 0, 0, 0, 0};
    if (bias) {
        #pragma unroll
        for (int j = 0; j < 8; j++) bv[j] = bias[col0 + j];
    }
    #pragma unroll
    for (int i = 0; i < 8; i++) {
        float4 c0 = {acc[i][0] + bv[0], acc[i][1] + bv[1],
                     acc[i][2] + bv[2], acc[i][3] + bv[3]};
        float4 c1 = {acc[i][4] + bv[4], acc[i][5] + bv[5],
                     acc[i][6] + bv[6], acc[i][7] + bv[7]};
        *(float4*)(C + (size_t)(row0 + i) * N + col0)     = c0;
        *(float4*)(C + (size_t)(row0 + i) * N + col0 + 4) = c1;
    }
}

// ---------------------------------------------------------------------------
// FlashAttention-2 with TF32 mma.sync (m16n8k8).
// Block: 256 threads = 8 warps; BQ=128 q-rows (16/warp), BKV=64 keys/tile.
// Q fragments preloaded to registers; K/V staged in smem (conflict-free
// strides for the B-fragment load patterns); softmax on C-fragment layout;
// P converted C->A layout via quad shuffles (no S smem buffer).
// ---------------------------------------------------------------------------
#define BQ  128
#define BKV 64
#define KS_STRIDE 68
#define VS_STRIDE 72

__device__ __forceinline__ unsigned f2tf32(float x) {
    unsigned r;
    asm("cvt.rna.tf32.f32 %0, %1;" : "=r"(r) : "f"(x));
    return r;
}

__device__ __forceinline__ void mma_tf32(
    float& c0, float& c1, float& c2, float& c3,
    unsigned a0, unsigned a1, unsigned a2, unsigned a3,
    unsigned b0, unsigned b1)
{
    asm volatile(
        "mma.sync.aligned.m16n8k8.row.col.f32.tf32.tf32.f32 "
        "{%0,%1,%2,%3}, {%4,%5,%6,%7}, {%8,%9}, {%0,%1,%2,%3};"
        : "+f"(c0), "+f"(c1), "+f"(c2), "+f"(c3)
        : "r"(a0), "r"(a1), "r"(a2), "r"(a3), "r"(b0), "r"(b1));
}

__global__ __launch_bounds__(256) void attn_kernel()
{
    __shared__ float Ks[BKV * KS_STRIDE];   // [key][d], stride 68
    __shared__ float Vs[BKV * VS_STRIDE];   // [key][d], stride 72

    const int tid  = threadIdx.x;
    const int lane = tid & 31;
    const int warp = tid >> 5;
    const int g    = lane >> 2;   // group id (row within fragment)
    const int q    = lane & 3;    // thread id in group

    const int qt = blockIdx.x;            // q tile 0..15
    const int bh = blockIdx.y;            // 0..31
    const int b  = bh >> 3;
    const int h  = bh & 7;

    const float* base = g_qkv + (size_t)b * SEQ * QKV_W + h * DHEAD;
    const int n0 = qt * BQ;

    const int qrow0 = n0 + warp * 16 + g;
    const int qrow1 = qrow0 + 8;

    // Preload Q fragments (A layout), pre-scaled, tf32-rounded.
    unsigned qa[8][4];
    #pragma unroll
    for (int t = 0; t < 8; t++) {
        int c = t * 8 + q;
        qa[t][0] = f2tf32(SCALE_F * base[(size_t)qrow0 * QKV_W + c]);
        qa[t][1] = f2tf32(SCALE_F * base[(size_t)qrow1 * QKV_W + c]);
        qa[t][2] = f2tf32(SCALE_F * base[(size_t)qrow0 * QKV_W + c + 4]);
        qa[t][3] = f2tf32(SCALE_F * base[(size_t)qrow1 * QKV_W + c + 4]);
    }

    float m0 = -1e30f, m1 = -1e30f;
    float l0 = 0.f,    l1 = 0.f;
    float o[8][4];
    #pragma unroll
    for (int n = 0; n < 8; n++)
        #pragma unroll
        for (int j = 0; j < 4; j++) o[n][j] = 0.f;

    for (int kt = 0; kt < SEQ / BKV; kt++) {
        const int kn0 = kt * BKV;

        // Stage K and V tiles (tf32-rounded) into smem.
        #pragma unroll
        for (int i = 0; i < 4; i++) {
            int f4  = tid + i * 256;          // 0..1023
            int row = f4 >> 4;
            int c4  = (f4 & 15) << 2;
            float4 kv = *(const float4*)(base + INNER +
                          (size_t)(kn0 + row) * QKV_W + c4);
            float4 vv = *(const float4*)(base + 2 * INNER +
                          (size_t)(kn0 + row) * QKV_W + c4);
            float4 kq = {__uint_as_float(f2tf32(kv.x)), __uint_as_float(f2tf32(kv.y)),
                         __uint_as_float(f2tf32(kv.z)), __uint_as_float(f2tf32(kv.w))};
            float4 vq = {__uint_as_float(f2tf32(vv.x)), __uint_as_float(f2tf32(vv.y)),
                         __uint_as_float(f2tf32(vv.z)), __uint_as_float(f2tf32(vv.w))};
            *(float4*)&Ks[row * KS_STRIDE + c4] = kq;
            *(float4*)&Vs[row * VS_STRIDE + c4] = vq;
        }
        __syncthreads();

        // S = Q @ K^T : 8 n-tiles (keys) x 8 k-steps (d)
        float c[8][4];
        #pragma unroll
        for (int n = 0; n < 8; n++)
            #pragma unroll
            for (int j = 0; j < 4; j++) c[n][j] = 0.f;

        #pragma unroll
        for (int k = 0; k < 8; k++) {
            #pragma unroll
            for (int n = 0; n < 8; n++) {
                // B[d][key]: b0 = K[key = n*8+g][d = k*8+q], b1 = +4 d
                unsigned b0 = __float_as_uint(Ks[(n * 8 + g) * KS_STRIDE + k * 8 + q]);
                unsigned b1 = __float_as_uint(Ks[(n * 8 + g) * KS_STRIDE + k * 8 + q + 4]);
                mma_tf32(c[n][0], c[n][1], c[n][2], c[n][3],
                         qa[k][0], qa[k][1], qa[k][2], qa[k][3], b0, b1);
            }
        }

        // Online softmax on C-fragment layout (rows g and g+8).
        float tm0 = -1e30f, tm1 = -1e30f;
        #pragma unroll
        for (int n = 0; n < 8; n++) {
            tm0 = fmaxf(tm0, fmaxf(c[n][0], c[n][1]));
            tm1 = fmaxf(tm1, fmaxf(c[n][2], c[n][3]));
        }
        #pragma unroll
        for (int off = 1; off < 4; off <<= 1) {
            tm0 = fmaxf(tm0, __shfl_xor_sync(0xffffffffu, tm0, off));
            tm1 = fmaxf(tm1, __shfl_xor_sync(0xffffffffu, tm1, off));
        }
        float nm0 = fmaxf(m0, tm0);
        float nm1 = fmaxf(m1, tm1);
        float al0 = __expf(m0 - nm0);
        float al1 = __expf(m1 - nm1);
        m0 = nm0; m1 = nm1;

        float s0 = 0.f, s1 = 0.f;
        #pragma unroll
        for (int n = 0; n < 8; n++) {
            c[n][0] = __expf(c[n][0] - m0);
            c[n][1] = __expf(c[n][1] - m0);
            c[n][2] = __expf(c[n][2] - m1);
            c[n][3] = __expf(c[n][3] - m1);
            s0 += c[n][0] + c[n][1];
            s1 += c[n][2] + c[n][3];
        }
        #pragma unroll
        for (int off = 1; off < 4; off <<= 1) {
            s0 += __shfl_xor_sync(0xffffffffu, s0, off);
            s1 += __shfl_xor_sync(0xffffffffu, s1, off);
        }
        l0 = l0 * al0 + s0;
        l1 = l1 * al1 + s1;

        #pragma unroll
        for (int n = 0; n < 8; n++) {
            o[n][0] *= al0; o[n][1] *= al0;
            o[n][2] *= al1; o[n][3] *= al1;
        }

        // O += P @ V : convert P C-frag -> A-frag via quad shuffles.
        #pragma unroll
        for (int k = 0; k < 8; k++) {
            int src_lo = (lane & ~3) | (q >> 1);
            int src_hi = src_lo + 2;
            float y00 = __shfl_sync(0xffffffffu, c[k][0], src_lo);
            float y01 = __shfl_sync(0xffffffffu, c[k][1], src_lo);
            float y10 = __shfl_sync(0xffffffffu, c[k][2], src_lo);
            float y11 = __shfl_sync(0xffffffffu, c[k][3], src_lo);
            float y20 = __shfl_sync(0xffffffffu, c[k][0], src_hi);
            float y21 = __shfl_sync(0xffffffffu, c[k][1], src_hi);
            float y30 = __shfl_sync(0xffffffffu, c[k][2], src_hi);
            float y31 = __shfl_sync(0xffffffffu, c[k][3], src_hi);
            bool odd = (q & 1);
            unsigned pa0 = f2tf32(odd ? y01 : y00);  // P[g   ][8k+q]
            unsigned pa1 = f2tf32(odd ? y11 : y10);  // P[g+8 ][8k+q]
            unsigned pa2 = f2tf32(odd ? y21 : y20);  // P[g   ][8k+q+4]
            unsigned pa3 = f2tf32(odd ? y31 : y30);  // P[g+8 ][8k+q+4]

            #pragma unroll
            for (int n = 0; n < 8; n++) {
                // B[key][d]: b0 = V[key = 8k+q][d = 8n+g], b1 = +4 key
                unsigned b0 = __float_as_uint(Vs[(k * 8 + q) * VS_STRIDE + n * 8 + g]);
                unsigned b1 = __float_as_uint(Vs[(k * 8 + q + 4) * VS_STRIDE + n * 8 + g]);
                mma_tf32(o[n][0], o[n][1], o[n][2], o[n][3],
                         pa0, pa1, pa2, pa3, b0, b1);
            }
        }
        __syncthreads();
    }

    // Normalize and write to g_attn [b, n, h*64 + d]
    float inv0 = 1.f / l0;
    float inv1 = 1.f / l1;
    #pragma unroll
    for (int n = 0; n < 8; n++) {
        int col = h * DHEAD + n * 8 + 2 * q;
        float2 r0 = {o[n][0] * inv0, o[n][1] * inv0};
        float2 r1 = {o[n][2] * inv1, o[n][3] * inv1};
        *(float2*)(g_attn + (size_t)(b * SEQ + qrow0) * INNER + col) = r0;
        *(float2*)(g_attn + (size_t)(b * SEQ + qrow1) * INNER + col) = r1;
    }
}

// ---------------------------------------------------------------------------
extern "C" void kernel_launch(void* const* d_in, const int* in_sizes, int n_in,
                              void* d_out, int out_size)
{
    const float* x     = (const float*)d_in[0];   // [4,2048,512]
    const float* w_qkv = (const float*)d_in[1];   // [512,1536]
    const float* w_out = (const float*)d_in[2];   // [512,512]
    const float* b_out = (const float*)d_in[3];   // [512]
    float* out = (float*)d_out;                   // [4,2048,512]

    const int M = BATCH * SEQ;                    // 8192

    // 1) qkv = x @ w_qkv  -> g_qkv
    dim3 g1(QKV_W / 128, M / 128);                // (12, 64)
    sgemm_kernel<<<g1, 256>>>(M, QKV_W, DIM, x, w_qkv, nullptr, nullptr, 1);

    // 2) attention -> g_attn
    dim3 g2(SEQ / BQ, BATCH * HEADS);             // (16, 32)
    attn_kernel<<<g2, 256>>>();

    // 3) out = g_attn @ w_out + b_out
    dim3 g3(DIM / 128, M / 128);                  // (4, 64)
    sgemm_kernel<<<g3, 256>>>(M, DIM, INNER, nullptr, w_out, b_out, out, 2);
}

// round 8
// speedup vs baseline: 4.3475x; 1.4021x over previous
#include <cuda_runtime.h>

#define BATCH   4
#define SEQ     2048
#define DIM     512
#define HEADS   8
#define DHEAD   64
#define INNER   512           // HEADS * DHEAD
#define QKV_W   (3 * INNER)   // 1536
#define SCALE_F 0.125f        // 64^-0.5

// Scratch (no allocations allowed): qkv projection + attention output
__device__ float g_qkv[(size_t)BATCH * SEQ * QKV_W];   // 12.58M floats
__device__ float g_attn[(size_t)BATCH * SEQ * INNER];  // 4.19M floats

__device__ __forceinline__ unsigned f2tf32(float x) {
    unsigned r;
    asm("cvt.rna.tf32.f32 %0, %1;" : "=r"(r) : "f"(x));
    return r;
}

__device__ __forceinline__ void mma_tf32(
    float& c0, float& c1, float& c2, float& c3,
    unsigned a0, unsigned a1, unsigned a2, unsigned a3,
    unsigned b0, unsigned b1)
{
    asm volatile(
        "mma.sync.aligned.m16n8k8.row.col.f32.tf32.tf32.f32 "
        "{%0,%1,%2,%3}, {%4,%5,%6,%7}, {%8,%9}, {%0,%1,%2,%3};"
        : "+f"(c0), "+f"(c1), "+f"(c2), "+f"(c3)
        : "r"(a0), "r"(a1), "r"(a2), "r"(a3), "r"(b0), "r"(b1));
}

// ---------------------------------------------------------------------------
// TF32 tensor-core GEMM: C[M,N] = A[M,K] @ B[K,N] (+ bias).
// 128x128 block tile, BK=16, 256 threads = 8 warps (4 over M x 2 over N),
// warp tile 32x64 (2 m-frags x 8 n-frags of m16n8k8).
// Smem stride 136 -> fragment LDS addresses (q*8+g) mod 32: conflict-free.
// SPLIT=true: 3-mma tf32 split (a_hi*b_hi + a_hi*b_lo + a_lo*b_hi) ~ fp32 acc.
// mode 1: C := g_qkv ; mode 2: A := g_attn
// ---------------------------------------------------------------------------
template <bool SPLIT>
__global__ __launch_bounds__(256, 2) void gemm_tf32_kernel(
    int M, int N, int K,
    const float* __restrict__ A,
    const float* __restrict__ B,
    const float* __restrict__ bias,
    float* __restrict__ C,
    int mode)
{
    if (mode == 1) C = g_qkv;
    if (mode == 2) A = g_attn;

    constexpr int BK  = 16;
    constexpr int AST = 136;   // stride: mod 32 == 8 -> conflict-free frag loads

    __shared__ float Ah[BK][AST];                      // A tile, K-major [k][m]
    __shared__ float Bh[BK][AST];                      // B tile, K-major [k][n]
    __shared__ float Al[SPLIT ? BK : 1][SPLIT ? AST : 1];
    __shared__ float Bl[SPLIT ? BK : 1][SPLIT ? AST : 1];

    const int tid  = threadIdx.x;
    const int lane = tid & 31;
    const int warp = tid >> 5;
    const int g    = lane >> 2;
    const int q    = lane & 3;
    const int wm   = (warp & 3) * 32;   // warp M offset in tile
    const int wn   = (warp >> 2) * 64;  // warp N offset in tile

    const float* Ab = A + (size_t)blockIdx.y * 128 * K;
    const float* Bb = B + (size_t)blockIdx.x * 128;

    float acc[2][8][4];
    #pragma unroll
    for (int mi = 0; mi < 2; mi++)
        #pragma unroll
        for (int ni = 0; ni < 8; ni++)
            #pragma unroll
            for (int j = 0; j < 4; j++) acc[mi][ni][j] = 0.f;

    for (int k0 = 0; k0 < K; k0 += BK) {
        // Stage A (transposed to K-major) and B, tf32-rounded (+ residuals).
        #pragma unroll
        for (int r = 0; r < 2; r++) {
            int f4 = tid + r * 256;                 // 0..511
            // A: 128 rows x 16 cols
            int arow = f4 >> 2;
            int ac4  = (f4 & 3) << 2;
            float4 av = *(const float4*)(Ab + (size_t)arow * K + k0 + ac4);
            float avals[4] = {av.x, av.y, av.z, av.w};
            #pragma unroll
            for (int j = 0; j < 4; j++) {
                unsigned hi = f2tf32(avals[j]);
                Ah[ac4 + j][arow] = __uint_as_float(hi);
                if (SPLIT)
                    Al[ac4 + j][arow] = __uint_as_float(
                        f2tf32(avals[j] - __uint_as_float(hi)));
            }
            // B: 16 rows x 128 cols
            int bk  = f4 >> 5;
            int bc4 = (f4 & 31) << 2;
            float4 bv = *(const float4*)(Bb + (size_t)(k0 + bk) * N + bc4);
            float bvals[4] = {bv.x, bv.y, bv.z, bv.w};
            #pragma unroll
            for (int j = 0; j < 4; j++) {
                unsigned hi = f2tf32(bvals[j]);
                Bh[bk][bc4 + j] = __uint_as_float(hi);
                if (SPLIT)
                    Bl[bk][bc4 + j] = __uint_as_float(
                        f2tf32(bvals[j] - __uint_as_float(hi)));
            }
        }
        __syncthreads();

        #pragma unroll
        for (int kk = 0; kk < BK / 8; kk++) {
            const int kr = kk * 8;
            unsigned ah[2][4], bh[8][2];
            unsigned al[2][4], bl[8][2];
            #pragma unroll
            for (int mi = 0; mi < 2; mi++) {
                int m0 = wm + mi * 16;
                ah[mi][0] = __float_as_uint(Ah[kr + q    ][m0 + g    ]);
                ah[mi][1] = __float_as_uint(Ah[kr + q    ][m0 + g + 8]);
                ah[mi][2] = __float_as_uint(Ah[kr + q + 4][m0 + g    ]);
                ah[mi][3] = __float_as_uint(Ah[kr + q + 4][m0 + g + 8]);
                if (SPLIT) {
                    al[mi][0] = __float_as_uint(Al[kr + q    ][m0 + g    ]);
                    al[mi][1] = __float_as_uint(Al[kr + q    ][m0 + g + 8]);
                    al[mi][2] = __float_as_uint(Al[kr + q + 4][m0 + g    ]);
                    al[mi][3] = __float_as_uint(Al[kr + q + 4][m0 + g + 8]);
                }
            }
            #pragma unroll
            for (int ni = 0; ni < 8; ni++) {
                int n0 = wn + ni * 8;
                bh[ni][0] = __float_as_uint(Bh[kr + q    ][n0 + g]);
                bh[ni][1] = __float_as_uint(Bh[kr + q + 4][n0 + g]);
                if (SPLIT) {
                    bl[ni][0] = __float_as_uint(Bl[kr + q    ][n0 + g]);
                    bl[ni][1] = __float_as_uint(Bl[kr + q + 4][n0 + g]);
                }
            }
            #pragma unroll
            for (int mi = 0; mi < 2; mi++)
                #pragma unroll
                for (int ni = 0; ni < 8; ni++) {
                    mma_tf32(acc[mi][ni][0], acc[mi][ni][1],
                             acc[mi][ni][2], acc[mi][ni][3],
                             ah[mi][0], ah[mi][1], ah[mi][2], ah[mi][3],
                             bh[ni][0], bh[ni][1]);
                    if (SPLIT) {
                        mma_tf32(acc[mi][ni][0], acc[mi][ni][1],
                                 acc[mi][ni][2], acc[mi][ni][3],
                                 ah[mi][0], ah[mi][1], ah[mi][2], ah[mi][3],
                                 bl[ni][0], bl[ni][1]);
                        mma_tf32(acc[mi][ni][0], acc[mi][ni][1],
                                 acc[mi][ni][2], acc[mi][ni][3],
                                 al[mi][0], al[mi][1], al[mi][2], al[mi][3],
                                 bh[ni][0], bh[ni][1]);
                    }
                }
        }
        __syncthreads();
    }

    // Epilogue: C-fragment rows g / g+8, cols 2q / 2q+1 per n8 tile.
    #pragma unroll
    for (int mi = 0; mi < 2; mi++) {
        int row0 = blockIdx.y * 128 + wm + mi * 16 + g;
        #pragma unroll
        for (int ni = 0; ni < 8; ni++) {
            int col = blockIdx.x * 128 + wn + ni * 8 + 2 * q;
            float b0 = 0.f, b1 = 0.f;
            if (bias) { b0 = bias[col]; b1 = bias[col + 1]; }
            float2 r0 = {acc[mi][ni][0] + b0, acc[mi][ni][1] + b1};
            float2 r1 = {acc[mi][ni][2] + b0, acc[mi][ni][3] + b1};
            *(float2*)(C + (size_t)row0 * N + col)       = r0;
            *(float2*)(C + (size_t)(row0 + 8) * N + col) = r1;
        }
    }
}

// ---------------------------------------------------------------------------
// FlashAttention-2 with TF32 mma.sync (m16n8k8). (unchanged from R5)
// ---------------------------------------------------------------------------
#define BQ  128
#define BKV 64
#define KS_STRIDE 68
#define VS_STRIDE 72

__global__ __launch_bounds__(256) void attn_kernel()
{
    __shared__ float Ks[BKV * KS_STRIDE];   // [key][d], stride 68
    __shared__ float Vs[BKV * VS_STRIDE];   // [key][d], stride 72

    const int tid  = threadIdx.x;
    const int lane = tid & 31;
    const int warp = tid >> 5;
    const int g    = lane >> 2;
    const int q    = lane & 3;

    const int qt = blockIdx.x;
    const int bh = blockIdx.y;
    const int b  = bh >> 3;
    const int h  = bh & 7;

    const float* base = g_qkv + (size_t)b * SEQ * QKV_W + h * DHEAD;
    const int n0 = qt * BQ;

    const int qrow0 = n0 + warp * 16 + g;
    const int qrow1 = qrow0 + 8;

    unsigned qa[8][4];
    #pragma unroll
    for (int t = 0; t < 8; t++) {
        int c = t * 8 + q;
        qa[t][0] = f2tf32(SCALE_F * base[(size_t)qrow0 * QKV_W + c]);
        qa[t][1] = f2tf32(SCALE_F * base[(size_t)qrow1 * QKV_W + c]);
        qa[t][2] = f2tf32(SCALE_F * base[(size_t)qrow0 * QKV_W + c + 4]);
        qa[t][3] = f2tf32(SCALE_F * base[(size_t)qrow1 * QKV_W + c + 4]);
    }

    float m0 = -1e30f, m1 = -1e30f;
    float l0 = 0.f,    l1 = 0.f;
    float o[8][4];
    #pragma unroll
    for (int n = 0; n < 8; n++)
        #pragma unroll
        for (int j = 0; j < 4; j++) o[n][j] = 0.f;

    for (int kt = 0; kt < SEQ / BKV; kt++) {
        const int kn0 = kt * BKV;

        #pragma unroll
        for (int i = 0; i < 4; i++) {
            int f4  = tid + i * 256;
            int row = f4 >> 4;
            int c4  = (f4 & 15) << 2;
            float4 kv = *(const float4*)(base + INNER +
                          (size_t)(kn0 + row) * QKV_W + c4);
            float4 vv = *(const float4*)(base + 2 * INNER +
                          (size_t)(kn0 + row) * QKV_W + c4);
            float4 kq = {__uint_as_float(f2tf32(kv.x)), __uint_as_float(f2tf32(kv.y)),
                         __uint_as_float(f2tf32(kv.z)), __uint_as_float(f2tf32(kv.w))};
            float4 vq = {__uint_as_float(f2tf32(vv.x)), __uint_as_float(f2tf32(vv.y)),
                         __uint_as_float(f2tf32(vv.z)), __uint_as_float(f2tf32(vv.w))};
            *(float4*)&Ks[row * KS_STRIDE + c4] = kq;
            *(float4*)&Vs[row * VS_STRIDE + c4] = vq;
        }
        __syncthreads();

        float c[8][4];
        #pragma unroll
        for (int n = 0; n < 8; n++)
            #pragma unroll
            for (int j = 0; j < 4; j++) c[n][j] = 0.f;

        #pragma unroll
        for (int k = 0; k < 8; k++) {
            #pragma unroll
            for (int n = 0; n < 8; n++) {
                unsigned b0 = __float_as_uint(Ks[(n * 8 + g) * KS_STRIDE + k * 8 + q]);
                unsigned b1 = __float_as_uint(Ks[(n * 8 + g) * KS_STRIDE + k * 8 + q + 4]);
                mma_tf32(c[n][0], c[n][1], c[n][2], c[n][3],
                         qa[k][0], qa[k][1], qa[k][2], qa[k][3], b0, b1);
            }
        }

        float tm0 = -1e30f, tm1 = -1e30f;
        #pragma unroll
        for (int n = 0; n < 8; n++) {
            tm0 = fmaxf(tm0, fmaxf(c[n][0], c[n][1]));
            tm1 = fmaxf(tm1, fmaxf(c[n][2], c[n][3]));
        }
        #pragma unroll
        for (int off = 1; off < 4; off <<= 1) {
            tm0 = fmaxf(tm0, __shfl_xor_sync(0xffffffffu, tm0, off));
            tm1 = fmaxf(tm1, __shfl_xor_sync(0xffffffffu, tm1, off));
        }
        float nm0 = fmaxf(m0, tm0);
        float nm1 = fmaxf(m1, tm1);
        float al0 = __expf(m0 - nm0);
        float al1 = __expf(m1 - nm1);
        m0 = nm0; m1 = nm1;

        float s0 = 0.f, s1 = 0.f;
        #pragma unroll
        for (int n = 0; n < 8; n++) {
            c[n][0] = __expf(c[n][0] - m0);
            c[n][1] = __expf(c[n][1] - m0);
            c[n][2] = __expf(c[n][2] - m1);
            c[n][3] = __expf(c[n][3] - m1);
            s0 += c[n][0] + c[n][1];
            s1 += c[n][2] + c[n][3];
        }
        #pragma unroll
        for (int off = 1; off < 4; off <<= 1) {
            s0 += __shfl_xor_sync(0xffffffffu, s0, off);
            s1 += __shfl_xor_sync(0xffffffffu, s1, off);
        }
        l0 = l0 * al0 + s0;
        l1 = l1 * al1 + s1;

        #pragma unroll
        for (int n = 0; n < 8; n++) {
            o[n][0] *= al0; o[n][1] *= al0;
            o[n][2] *= al1; o[n][3] *= al1;
        }

        #pragma unroll
        for (int k = 0; k < 8; k++) {
            int src_lo = (lane & ~3) | (q >> 1);
            int src_hi = src_lo + 2;
            float y00 = __shfl_sync(0xffffffffu, c[k][0], src_lo);
            float y01 = __shfl_sync(0xffffffffu, c[k][1], src_lo);
            float y10 = __shfl_sync(0xffffffffu, c[k][2], src_lo);
            float y11 = __shfl_sync(0xffffffffu, c[k][3], src_lo);
            float y20 = __shfl_sync(0xffffffffu, c[k][0], src_hi);
            float y21 = __shfl_sync(0xffffffffu, c[k][1], src_hi);
            float y30 = __shfl_sync(0xffffffffu, c[k][2], src_hi);
            float y31 = __shfl_sync(0xffffffffu, c[k][3], src_hi);
            bool odd = (q & 1);
            unsigned pa0 = f2tf32(odd ? y01 : y00);
            unsigned pa1 = f2tf32(odd ? y11 : y10);
            unsigned pa2 = f2tf32(odd ? y21 : y20);
            unsigned pa3 = f2tf32(odd ? y31 : y30);

            #pragma unroll
            for (int n = 0; n < 8; n++) {
                unsigned b0 = __float_as_uint(Vs[(k * 8 + q) * VS_STRIDE + n * 8 + g]);
                unsigned b1 = __float_as_uint(Vs[(k * 8 + q + 4) * VS_STRIDE + n * 8 + g]);
                mma_tf32(o[n][0], o[n][1], o[n][2], o[n][3],
                         pa0, pa1, pa2, pa3, b0, b1);
            }
        }
        __syncthreads();
    }

    float inv0 = 1.f / l0;
    float inv1 = 1.f / l1;
    #pragma unroll
    for (int n = 0; n < 8; n++) {
        int col = h * DHEAD + n * 8 + 2 * q;
        float2 r0 = {o[n][0] * inv0, o[n][1] * inv0};
        float2 r1 = {o[n][2] * inv1, o[n][3] * inv1};
        *(float2*)(g_attn + (size_t)(b * SEQ + qrow0) * INNER + col) = r0;
        *(float2*)(g_attn + (size_t)(b * SEQ + qrow1) * INNER + col) = r1;
    }
}

// ---------------------------------------------------------------------------
extern "C" void kernel_launch(void* const* d_in, const int* in_sizes, int n_in,
                              void* d_out, int out_size)
{
    const float* x     = (const float*)d_in[0];   // [4,2048,512]
    const float* w_qkv = (const float*)d_in[1];   // [512,1536]
    const float* w_out = (const float*)d_in[2];   // [512,512]
    const float* b_out = (const float*)d_in[3];   // [512]
    float* out = (float*)d_out;                   // [4,2048,512]

    const int M = BATCH * SEQ;                    // 8192

    // 1) qkv = x @ w_qkv  -> g_qkv   (single-pass TF32)
    dim3 g1(QKV_W / 128, M / 128);                // (12, 64)
    gemm_tf32_kernel<false><<<g1, 256>>>(M, QKV_W, DIM, x, w_qkv,
                                         nullptr, nullptr, 1);

    // 2) attention -> g_attn
    dim3 g2(SEQ / BQ, BATCH * HEADS);             // (16, 32)
    attn_kernel<<<g2, 256>>>();

    // 3) out = g_attn @ w_out + b_out   (3-mma split TF32 ~ fp32 accuracy)
    dim3 g3(DIM / 128, M / 128);                  // (4, 64)
    gemm_tf32_kernel<true><<<g3, 256>>>(M, DIM, INNER, nullptr, w_out,
                                        b_out, out, 2);
}

// round 11
// speedup vs baseline: 4.4133x; 1.0151x over previous
#include <cuda_runtime.h>

#define BATCH   4
#define SEQ     2048
#define DIM     512
#define HEADS   8
#define DHEAD   64
#define INNER   512           // HEADS * DHEAD
#define QKV_W   (3 * INNER)   // 1536
#define SCALE_F 0.125f        // 64^-0.5

// Scratch (no allocations allowed): qkv projection + attention output
__device__ float g_qkv[(size_t)BATCH * SEQ * QKV_W];   // 12.58M floats
__device__ float g_attn[(size_t)BATCH * SEQ * INNER];  // 4.19M floats

__device__ __forceinline__ unsigned f2tf32(float x) {
    unsigned r;
    asm("cvt.rna.tf32.f32 %0, %1;" : "=r"(r) : "f"(x));
    return r;
}

__device__ __forceinline__ void mma_tf32(
    float& c0, float& c1, float& c2, float& c3,
    unsigned a0, unsigned a1, unsigned a2, unsigned a3,
    unsigned b0, unsigned b1)
{
    asm volatile(
        "mma.sync.aligned.m16n8k8.row.col.f32.tf32.tf32.f32 "
        "{%0,%1,%2,%3}, {%4,%5,%6,%7}, {%8,%9}, {%0,%1,%2,%3};"
        : "+f"(c0), "+f"(c1), "+f"(c2), "+f"(c3)
        : "r"(a0), "r"(a1), "r"(a2), "r"(a3), "r"(b0), "r"(b1));
}

__device__ __forceinline__ void ldmx4(
    unsigned& r0, unsigned& r1, unsigned& r2, unsigned& r3, const void* p)
{
    unsigned addr = (unsigned)__cvta_generic_to_shared(p);
    asm volatile(
        "ldmatrix.sync.aligned.m8n8.x4.shared.b16 {%0,%1,%2,%3}, [%4];"
        : "=r"(r0), "=r"(r1), "=r"(r2), "=r"(r3) : "r"(addr));
}

// ---------------------------------------------------------------------------
// TF32 tensor-core GEMM, register-prefetch software pipeline.
// C[M,N] = A[M,K] @ B[K,N] (+ bias). 128x128 tile, BK=16, 8 warps (4x2),
// warp tile 32x64. Smem stride 136 -> conflict-free fragment LDS.
// SPLIT=true: 3-mma tf32 split for ~fp32 accuracy.
// mode 1: C := g_qkv ; mode 2: A := g_attn
// ---------------------------------------------------------------------------
template <bool SPLIT>
__global__ __launch_bounds__(256, 2) void gemm_tf32_kernel(
    int M, int N, int K,
    const float* __restrict__ A,
    const float* __restrict__ B,
    const float* __restrict__ bias,
    float* __restrict__ C,
    int mode)
{
    if (mode == 1) C = g_qkv;
    if (mode == 2) A = g_attn;

    constexpr int BK  = 16;
    constexpr int AST = 136;

    __shared__ float Ah[BK][AST];
    __shared__ float Bh[BK][AST];
    __shared__ float Al[SPLIT ? BK : 1][SPLIT ? AST : 1];
    __shared__ float Bl[SPLIT ? BK : 1][SPLIT ? AST : 1];

    const int tid  = threadIdx.x;
    const int lane = tid & 31;
    const int warp = tid >> 5;
    const int g    = lane >> 2;
    const int q    = lane & 3;
    const int wm   = (warp & 3) * 32;
    const int wn   = (warp >> 2) * 64;

    const float* Ab = A + (size_t)blockIdx.y * 128 * K;
    const float* Bb = B + (size_t)blockIdx.x * 128;

    // Per-thread staging coordinates (2 float4 each for A and B)
    const int arow = tid >> 2;            // 0..63 ; second row arow+64
    const int ac4  = (tid & 3) << 2;      // 0,4,8,12
    const int brow = tid >> 5;            // 0..7  ; second row brow+8
    const int bc4  = (tid & 31) << 2;     // 0..124

    float acc[2][8][4];
    #pragma unroll
    for (int mi = 0; mi < 2; mi++)
        #pragma unroll
        for (int ni = 0; ni < 8; ni++)
            #pragma unroll
            for (int j = 0; j < 4; j++) acc[mi][ni][j] = 0.f;

    // Prefetch first tile into registers
    float4 pa0 = *(const float4*)(Ab + (size_t)arow * K + ac4);
    float4 pa1 = *(const float4*)(Ab + (size_t)(arow + 64) * K + ac4);
    float4 pb0 = *(const float4*)(Bb + (size_t)brow * N + bc4);
    float4 pb1 = *(const float4*)(Bb + (size_t)(brow + 8) * N + bc4);

    for (int k0 = 0; k0 < K; k0 += BK) {
        // Store prefetched tile to smem (tf32-rounded, + residuals if SPLIT)
        {
            float av0[4] = {pa0.x, pa0.y, pa0.z, pa0.w};
            float av1[4] = {pa1.x, pa1.y, pa1.z, pa1.w};
            float bv0[4] = {pb0.x, pb0.y, pb0.z, pb0.w};
            float bv1[4] = {pb1.x, pb1.y, pb1.z, pb1.w};
            #pragma unroll
            for (int j = 0; j < 4; j++) {
                unsigned h0 = f2tf32(av0[j]);
                unsigned h1 = f2tf32(av1[j]);
                Ah[ac4 + j][arow]      = __uint_as_float(h0);
                Ah[ac4 + j][arow + 64] = __uint_as_float(h1);
                if (SPLIT) {
                    Al[ac4 + j][arow]      = __uint_as_float(
                        f2tf32(av0[j] - __uint_as_float(h0)));
                    Al[ac4 + j][arow + 64] = __uint_as_float(
                        f2tf32(av1[j] - __uint_as_float(h1)));
                }
                unsigned g0 = f2tf32(bv0[j]);
                unsigned g1 = f2tf32(bv1[j]);
                Bh[brow][bc4 + j]     = __uint_as_float(g0);
                Bh[brow + 8][bc4 + j] = __uint_as_float(g1);
                if (SPLIT) {
                    Bl[brow][bc4 + j]     = __uint_as_float(
                        f2tf32(bv0[j] - __uint_as_float(g0)));
                    Bl[brow + 8][bc4 + j] = __uint_as_float(
                        f2tf32(bv1[j] - __uint_as_float(g1)));
                }
            }
        }
        __syncthreads();

        // Issue next tile's global loads (consumed at next iteration's store)
        if (k0 + BK < K) {
            int kn = k0 + BK;
            pa0 = *(const float4*)(Ab + (size_t)arow * K + kn + ac4);
            pa1 = *(const float4*)(Ab + (size_t)(arow + 64) * K + kn + ac4);
            pb0 = *(const float4*)(Bb + (size_t)(kn + brow) * N + bc4);
            pb1 = *(const float4*)(Bb + (size_t)(kn + brow + 8) * N + bc4);
        }

        #pragma unroll
        for (int kk = 0; kk < BK / 8; kk++) {
            const int kr = kk * 8;
            unsigned ah[2][4], bh[8][2];
            unsigned al[2][4], bl[8][2];
            #pragma unroll
            for (int mi = 0; mi < 2; mi++) {
                int m0 = wm + mi * 16;
                ah[mi][0] = __float_as_uint(Ah[kr + q    ][m0 + g    ]);
                ah[mi][1] = __float_as_uint(Ah[kr + q    ][m0 + g + 8]);
                ah[mi][2] = __float_as_uint(Ah[kr + q + 4][m0 + g    ]);
                ah[mi][3] = __float_as_uint(Ah[kr + q + 4][m0 + g + 8]);
                if (SPLIT) {
                    al[mi][0] = __float_as_uint(Al[kr + q    ][m0 + g    ]);
                    al[mi][1] = __float_as_uint(Al[kr + q    ][m0 + g + 8]);
                    al[mi][2] = __float_as_uint(Al[kr + q + 4][m0 + g    ]);
                    al[mi][3] = __float_as_uint(Al[kr + q + 4][m0 + g + 8]);
                }
            }
            #pragma unroll
            for (int ni = 0; ni < 8; ni++) {
                int n0 = wn + ni * 8;
                bh[ni][0] = __float_as_uint(Bh[kr + q    ][n0 + g]);
                bh[ni][1] = __float_as_uint(Bh[kr + q + 4][n0 + g]);
                if (SPLIT) {
                    bl[ni][0] = __float_as_uint(Bl[kr + q    ][n0 + g]);
                    bl[ni][1] = __float_as_uint(Bl[kr + q + 4][n0 + g]);
                }
            }
            #pragma unroll
            for (int mi = 0; mi < 2; mi++)
                #pragma unroll
                for (int ni = 0; ni < 8; ni++) {
                    mma_tf32(acc[mi][ni][0], acc[mi][ni][1],
                             acc[mi][ni][2], acc[mi][ni][3],
                             ah[mi][0], ah[mi][1], ah[mi][2], ah[mi][3],
                             bh[ni][0], bh[ni][1]);
                    if (SPLIT) {
                        mma_tf32(acc[mi][ni][0], acc[mi][ni][1],
                                 acc[mi][ni][2], acc[mi][ni][3],
                                 ah[mi][0], ah[mi][1], ah[mi][2], ah[mi][3],
                                 bl[ni][0], bl[ni][1]);
                        mma_tf32(acc[mi][ni][0], acc[mi][ni][1],
                                 acc[mi][ni][2], acc[mi][ni][3],
                                 al[mi][0], al[mi][1], al[mi][2], al[mi][3],
                                 bh[ni][0], bh[ni][1]);
                    }
                }
        }
        __syncthreads();
    }

    #pragma unroll
    for (int mi = 0; mi < 2; mi++) {
        int row0 = blockIdx.y * 128 + wm + mi * 16 + g;
        #pragma unroll
        for (int ni = 0; ni < 8; ni++) {
            int col = blockIdx.x * 128 + wn + ni * 8 + 2 * q;
            float b0 = 0.f, b1 = 0.f;
            if (bias) { b0 = bias[col]; b1 = bias[col + 1]; }
            float2 r0 = {acc[mi][ni][0] + b0, acc[mi][ni][1] + b1};
            float2 r1 = {acc[mi][ni][2] + b0, acc[mi][ni][3] + b1};
            *(float2*)(C + (size_t)row0 * N + col)       = r0;
            *(float2*)(C + (size_t)(row0 + 8) * N + col) = r1;
        }
    }
}

// ---------------------------------------------------------------------------
// FlashAttention-2, TF32 mma.sync. S-phase B-fragments now via ldmatrix.x4:
// one instruction yields b0/b1 for TWO k-steps (4 m8n8 matrices = word-cols
// kr..kr+15 of 8 key rows). Ks stride 68 -> ldmatrix row banks 4r+off,
// conflict-free. PV phase unchanged.
// ---------------------------------------------------------------------------
#define BQ  128
#define BKV 64
#define KS_STRIDE 68
#define VS_STRIDE 72

__global__ __launch_bounds__(256) void attn_kernel()
{
    __shared__ float Ks[BKV * KS_STRIDE];
    __shared__ float Vs[BKV * VS_STRIDE];

    const int tid  = threadIdx.x;
    const int lane = tid & 31;
    const int warp = tid >> 5;
    const int g    = lane >> 2;
    const int q    = lane & 3;
    const int rl   = lane & 7;    // ldmatrix row within matrix
    const int jj   = lane >> 3;   // ldmatrix matrix index 0..3

    const int qt = blockIdx.x;
    const int bh = blockIdx.y;
    const int b  = bh >> 3;
    const int h  = bh & 7;

    const float* base = g_qkv + (size_t)b * SEQ * QKV_W + h * DHEAD;
    const int n0 = qt * BQ;

    const int qrow0 = n0 + warp * 16 + g;
    const int qrow1 = qrow0 + 8;

    unsigned qa[8][4];
    #pragma unroll
    for (int t = 0; t < 8; t++) {
        int c = t * 8 + q;
        qa[t][0] = f2tf32(SCALE_F * base[(size_t)qrow0 * QKV_W + c]);
        qa[t][1] = f2tf32(SCALE_F * base[(size_t)qrow1 * QKV_W + c]);
        qa[t][2] = f2tf32(SCALE_F * base[(size_t)qrow0 * QKV_W + c + 4]);
        qa[t][3] = f2tf32(SCALE_F * base[(size_t)qrow1 * QKV_W + c + 4]);
    }

    // Per-lane ldmatrix base: row rl, word-col 4*jj
    const float* kldm = Ks + (size_t)rl * KS_STRIDE + 4 * jj;

    float m0 = -1e30f, m1 = -1e30f;
    float l0 = 0.f,    l1 = 0.f;
    float o[8][4];
    #pragma unroll
    for (int n = 0; n < 8; n++)
        #pragma unroll
        for (int j = 0; j < 4; j++) o[n][j] = 0.f;

    for (int kt = 0; kt < SEQ / BKV; kt++) {
        const int kn0 = kt * BKV;

        #pragma unroll
        for (int i = 0; i < 4; i++) {
            int f4  = tid + i * 256;
            int row = f4 >> 4;
            int c4  = (f4 & 15) << 2;
            float4 kv = *(const float4*)(base + INNER +
                          (size_t)(kn0 + row) * QKV_W + c4);
            float4 vv = *(const float4*)(base + 2 * INNER +
                          (size_t)(kn0 + row) * QKV_W + c4);
            float4 kq = {__uint_as_float(f2tf32(kv.x)), __uint_as_float(f2tf32(kv.y)),
                         __uint_as_float(f2tf32(kv.z)), __uint_as_float(f2tf32(kv.w))};
            float4 vq = {__uint_as_float(f2tf32(vv.x)), __uint_as_float(f2tf32(vv.y)),
                         __uint_as_float(f2tf32(vv.z)), __uint_as_float(f2tf32(vv.w))};
            *(float4*)&Ks[row * KS_STRIDE + c4] = kq;
            *(float4*)&Vs[row * VS_STRIDE + c4] = vq;
        }
        __syncthreads();

        // S = Q @ K^T : ldmatrix.x4 per (n, k-pair)
        float c[8][4];
        #pragma unroll
        for (int n = 0; n < 8; n++)
            #pragma unroll
            for (int j = 0; j < 4; j++) c[n][j] = 0.f;

        #pragma unroll
        for (int k = 0; k < 8; k += 2) {
            #pragma unroll
            for (int n = 0; n < 8; n++) {
                unsigned b0, b1, b2, b3;
                ldmx4(b0, b1, b2, b3, kldm + (size_t)n * 8 * KS_STRIDE + k * 8);
                mma_tf32(c[n][0], c[n][1], c[n][2], c[n][3],
                         qa[k][0], qa[k][1], qa[k][2], qa[k][3], b0, b1);
                mma_tf32(c[n][0], c[n][1], c[n][2], c[n][3],
                         qa[k+1][0], qa[k+1][1], qa[k+1][2], qa[k+1][3], b2, b3);
            }
        }

        // Online softmax on C-fragment layout
        float tm0 = -1e30f, tm1 = -1e30f;
        #pragma unroll
        for (int n = 0; n < 8; n++) {
            tm0 = fmaxf(tm0, fmaxf(c[n][0], c[n][1]));
            tm1 = fmaxf(tm1, fmaxf(c[n][2], c[n][3]));
        }
        #pragma unroll
        for (int off = 1; off < 4; off <<= 1) {
            tm0 = fmaxf(tm0, __shfl_xor_sync(0xffffffffu, tm0, off));
            tm1 = fmaxf(tm1, __shfl_xor_sync(0xffffffffu, tm1, off));
        }
        float nm0 = fmaxf(m0, tm0);
        float nm1 = fmaxf(m1, tm1);
        float al0 = __expf(m0 - nm0);
        float al1 = __expf(m1 - nm1);
        m0 = nm0; m1 = nm1;

        float s0 = 0.f, s1 = 0.f;
        #pragma unroll
        for (int n = 0; n < 8; n++) {
            c[n][0] = __expf(c[n][0] - m0);
            c[n][1] = __expf(c[n][1] - m0);
            c[n][2] = __expf(c[n][2] - m1);
            c[n][3] = __expf(c[n][3] - m1);
            s0 += c[n][0] + c[n][1];
            s1 += c[n][2] + c[n][3];
        }
        #pragma unroll
        for (int off = 1; off < 4; off <<= 1) {
            s0 += __shfl_xor_sync(0xffffffffu, s0, off);
            s1 += __shfl_xor_sync(0xffffffffu, s1, off);
        }
        l0 = l0 * al0 + s0;
        l1 = l1 * al1 + s1;

        #pragma unroll
        for (int n = 0; n < 8; n++) {
            o[n][0] *= al0; o[n][1] *= al0;
            o[n][2] *= al1; o[n][3] *= al1;
        }

        // O += P @ V : P C-frag -> A-frag via quad shuffles; V scalar LDS
        #pragma unroll
        for (int k = 0; k < 8; k++) {
            int src_lo = (lane & ~3) | (q >> 1);
            int src_hi = src_lo + 2;
            float y00 = __shfl_sync(0xffffffffu, c[k][0], src_lo);
            float y01 = __shfl_sync(0xffffffffu, c[k][1], src_lo);
            float y10 = __shfl_sync(0xffffffffu, c[k][2], src_lo);
            float y11 = __shfl_sync(0xffffffffu, c[k][3], src_lo);
            float y20 = __shfl_sync(0xffffffffu, c[k][0], src_hi);
            float y21 = __shfl_sync(0xffffffffu, c[k][1], src_hi);
            float y30 = __shfl_sync(0xffffffffu, c[k][2], src_hi);
            float y31 = __shfl_sync(0xffffffffu, c[k][3], src_hi);
            bool odd = (q & 1);
            unsigned pa0 = f2tf32(odd ? y01 : y00);
            unsigned pa1 = f2tf32(odd ? y11 : y10);
            unsigned pa2 = f2tf32(odd ? y21 : y20);
            unsigned pa3 = f2tf32(odd ? y31 : y30);

            #pragma unroll
            for (int n = 0; n < 8; n++) {
                unsigned b0 = __float_as_uint(Vs[(k * 8 + q) * VS_STRIDE + n * 8 + g]);
                unsigned b1 = __float_as_uint(Vs[(k * 8 + q + 4) * VS_STRIDE + n * 8 + g]);
                mma_tf32(o[n][0], o[n][1], o[n][2], o[n][3],
                         pa0, pa1, pa2, pa3, b0, b1);
            }
        }
        __syncthreads();
    }

    float inv0 = 1.f / l0;
    float inv1 = 1.f / l1;
    #pragma unroll
    for (int n = 0; n < 8; n++) {
        int col = h * DHEAD + n * 8 + 2 * q;
        float2 r0 = {o[n][0] * inv0, o[n][1] * inv0};
        float2 r1 = {o[n][2] * inv1, o[n][3] * inv1};
        *(float2*)(g_attn + (size_t)(b * SEQ + qrow0) * INNER + col) = r0;
        *(float2*)(g_attn + (size_t)(b * SEQ + qrow1) * INNER + col) = r1;
    }
}

// ---------------------------------------------------------------------------
extern "C" void kernel_launch(void* const* d_in, const int* in_sizes, int n_in,
                              void* d_out, int out_size)
{
    const float* x     = (const float*)d_in[0];   // [4,2048,512]
    const float* w_qkv = (const float*)d_in[1];   // [512,1536]
    const float* w_out = (const float*)d_in[2];   // [512,512]
    const float* b_out = (const float*)d_in[3];   // [512]
    float* out = (float*)d_out;                   // [4,2048,512]

    const int M = BATCH * SEQ;                    // 8192

    dim3 g1(QKV_W / 128, M / 128);                // (12, 64)
    gemm_tf32_kernel<false><<<g1, 256>>>(M, QKV_W, DIM, x, w_qkv,
                                         nullptr, nullptr, 1);

    dim3 g2(SEQ / BQ, BATCH * HEADS);             // (16, 32)
    attn_kernel<<<g2, 256>>>();

    dim3 g3(DIM / 128, M / 128);                  // (4, 64)
    gemm_tf32_kernel<true><<<g3, 256>>>(M, DIM, INNER, nullptr, w_out,
                                        b_out, out, 2);
}